// round 4
// baseline (speedup 1.0000x reference)
#include <cuda_runtime.h>

// YOLOv1 loss, S=7, B=2, C=20, D=30, BATCH=16384
// NCELLS = 16384*49 = 802816 cells, each with 30 floats in t and p.

#define D_ELEMS 30
#define NCELLS 802816
#define CPB 128                       // cells (== threads) per block
#define NBLOCKS (NCELLS / CPB)        // 6272, exact
#define N4 (CPB * D_ELEMS / 4)        // 960 float4 per tensor per block

__device__ float g_partials[NBLOCKS];

__device__ __forceinline__ float sq(float x) { return x * x; }

__global__ __launch_bounds__(CPB) void yolo_main(const float* __restrict__ t_g,
                                                 const float* __restrict__ p_g) {
    __shared__ float st[CPB * D_ELEMS];
    __shared__ float sp[CPB * D_ELEMS];
    const int tid = threadIdx.x;
    const long long base = (long long)blockIdx.x * (CPB * D_ELEMS);

    // Stage: perfectly coalesced float4 copy gmem -> smem (linear layout).
    const float4* tg4 = reinterpret_cast<const float4*>(t_g + base);
    const float4* pg4 = reinterpret_cast<const float4*>(p_g + base);
    float4* st4 = reinterpret_cast<float4*>(st);
    float4* sp4 = reinterpret_cast<float4*>(sp);
#pragma unroll
    for (int j = tid; j < N4; j += CPB) {
        st4[j] = tg4[j];
        sp4[j] = pg4[j];
    }
    __syncthreads();

    const float* t = st + tid * D_ELEMS;
    const float* p = sp + tid * D_ELEMS;

    const float b0 = t[0], b1 = t[1], b2 = t[2], b3 = t[3], t4 = t[4];
    const float p0 = p[0], p1 = p[1], p2 = p[2], p3 = p[3], p4v = p[4];
    const float q0 = p[5], q1 = p[6], q2 = p[7], q3 = p[8], p9v = p[9];

    // IoU(b, bhat1) and IoU(b, bhat2), exactly mirroring the reference math.
    const float ax1 = b0 - b2 * 0.5f, ay1 = b1 - b3 * 0.5f;
    const float ax2 = b0 + b2 * 0.5f, ay2 = b1 + b3 * 0.5f;
    const float area_a = fabsf((ax2 - ax1) * (ay2 - ay1));

    const float bx1 = p0 - p2 * 0.5f, by1 = p1 - p3 * 0.5f;
    const float bx2 = p0 + p2 * 0.5f, by2 = p1 + p3 * 0.5f;
    const float iw1 = fmaxf(fminf(ax2, bx2) - fmaxf(ax1, bx1), 0.0f);
    const float ih1 = fmaxf(fminf(ay2, by2) - fmaxf(ay1, by1), 0.0f);
    const float inter1 = iw1 * ih1;
    const float area_b = fabsf((bx2 - bx1) * (by2 - by1));
    const float iou1 = inter1 / (area_a + area_b - inter1 + 1e-6f);

    const float cx1 = q0 - q2 * 0.5f, cy1 = q1 - q3 * 0.5f;
    const float cx2 = q0 + q2 * 0.5f, cy2 = q1 + q3 * 0.5f;
    const float iw2 = fmaxf(fminf(ax2, cx2) - fmaxf(ax1, cx1), 0.0f);
    const float ih2 = fmaxf(fminf(ay2, cy2) - fmaxf(ay1, cy1), 0.0f);
    const float inter2 = iw2 * ih2;
    const float area_c = fabsf((cx2 - cx1) * (cy2 - cy1));
    const float iou2 = inter2 / (area_a + area_c - inter2 + 1e-6f);

    const bool use1 = iou1 > iou2;
    const float bh0 = use1 ? p0 : q0;
    const float bh1 = use1 ? p1 : q1;
    const float bh2 = use1 ? p2 : q2;
    const float bh3 = use1 ? p3 : q3;
    const float chosen = use1 ? p4v : p9v;
    const float other  = use1 ? p9v : p4v;

    const float xy = 5.0f * (sq(b0 - bh0) + sq(b1 - bh1));
    const float wh = 5.0f * (sq(sqrtf(b2) - sqrtf(fabsf(bh2 + 1e-6f))) +
                             sq(sqrtf(b3) - sqrtf(fabsf(bh3 + 1e-6f))));
    const float obj_conf = sq(t4 - chosen);
    const float noobj_in_obj = 0.5f * sq(other);   // (0 - other)^2

    float cls = 0.0f;
#pragma unroll
    for (int k = 10; k < 30; k++) cls += sq(t[k] - p[k]);

    const float obj_terms = xy + wh + obj_conf + noobj_in_obj + cls;
    const float noobj_terms = 0.5f * (sq(t4 - p4v) + sq(t4 - p9v));

    float v = (t4 == 1.0f) ? obj_terms : noobj_terms;

    // Block reduction: warp shuffle tree, then per-warp partials in smem.
#pragma unroll
    for (int off = 16; off > 0; off >>= 1)
        v += __shfl_down_sync(0xffffffffu, v, off);

    __shared__ float wsum[CPB / 32];
    if ((tid & 31) == 0) wsum[tid >> 5] = v;
    __syncthreads();
    if (tid == 0) {
        float s = 0.0f;
#pragma unroll
        for (int w = 0; w < CPB / 32; w++) s += wsum[w];
        g_partials[blockIdx.x] = s;
    }
}

__global__ __launch_bounds__(256) void yolo_reduce(float* __restrict__ out) {
    // Double accumulation: 6272 partials, keeps final rounding negligible.
    double s = 0.0;
    for (int i = threadIdx.x; i < NBLOCKS; i += 256)
        s += (double)g_partials[i];
#pragma unroll
    for (int off = 16; off > 0; off >>= 1)
        s += __shfl_down_sync(0xffffffffu, s, off);

    __shared__ double wsumd[8];
    if ((threadIdx.x & 31) == 0) wsumd[threadIdx.x >> 5] = s;
    __syncthreads();
    if (threadIdx.x == 0) {
        double tot = 0.0;
#pragma unroll
        for (int w = 0; w < 8; w++) tot += wsumd[w];
        out[0] = (float)(tot / 16384.0);
    }
}

extern "C" void kernel_launch(void* const* d_in, const int* in_sizes, int n_in,
                              void* d_out, int out_size) {
    const float* y_trues = (const float*)d_in[0];
    const float* y_preds = (const float*)d_in[1];
    float* out = (float*)d_out;

    yolo_main<<<NBLOCKS, CPB>>>(y_trues, y_preds);
    yolo_reduce<<<1, 256>>>(out);
}